// round 13
// baseline (speedup 1.0000x reference)
#include <cuda_runtime.h>
#include <cuda_bf16.h>
#include <cstdint>

// DistortionLoss, O(N) per row, telescoped + T-deferred:
//   loss = inv * [ T*sum_e g_e*P_e - sum_e g_e*P_e^2 + (1/3)*sum w_i^2*dz_i ]
//   g_e = z_{e+1}-z_{e-1}, P_e = exclusive w prefix, T = total w,
//   inv = 1/(far-near). The e=0 term has P_0 = 0, so lane 0's zm1 is a
//   don't-care (any in-bounds value).
//
// Converged configuration (best ncu-measured across 12 rounds):
//  - z loaded as ONE aligned LDG.128 per lane from the 16B-floor base
//    (row*129 - s, s = row&3): minimal L1tex wavefronts (~11/warp) —
//    the single biggest measured win (L1% 21 -> 14, ncu 6.05 -> 5.63).
//  - minimal warp-uniform shfl recovery (avg 2.75 shfls vs 5).
//  - T combined into the partial BEFORE a single 5-step butterfly.
//  - inv (MUFU.RCP) hoisted to overlap the shfl chains.
//  - 256-thread blocks, grid 1024 (best ncu duration of 128/256/512 sweep).
//  - exact-grid fast path: no per-warp bounds guard when grid covers R.

#define FULL 0xffffffffu

template<bool GUARD>
__global__ __launch_bounds__(256)
void distortion_loss_kernel(const float* __restrict__ w,
                            const float* __restrict__ z,
                            const float* __restrict__ nearv,
                            const float* __restrict__ farv,
                            float* __restrict__ out,
                            int R)
{
    const int row  = (blockIdx.x * blockDim.x + threadIdx.x) >> 5;
    const int lane = threadIdx.x & 31;
    if (GUARD && row >= R) return;

    const int s = row & 3;                                   // warp-uniform
    const float* zrow = z + (size_t)row * 129;
    const float4* zc  = reinterpret_cast<const float4*>(zrow - s);  // aligned

    // ---- front-batched loads ----
    const float4 own = __ldg(zc + lane);                     // z[4l-s .. 4l-s+3]
    const float4 w4  = __ldg(reinterpret_cast<const float4*>(w + (size_t)row * 128) + lane);
    const float nr = __ldg(&nearv[row]);
    const float fr = __ldg(&farv[row]);

    // reciprocal issued early: MUFU latency overlaps the shfl chains below
    const float inv = __fdividef(1.0f, fr - nr);

    // ---- recover z[4l-1 .. 4l+4] with minimal shfls (warp-uniform switch) ----
    float zm1, z0, z1, z2, z3, z4;
    switch (s) {
        case 0: {
            float a = __shfl_down_sync(FULL, own.x, 1);      // z[4l+4]
            float b = __shfl_up_sync(FULL, own.w, 1);        // z[4l-1] (lane0 dc)
            if (lane == 31) a = __ldg(zrow + 128);
            zm1 = b; z0 = own.x; z1 = own.y; z2 = own.z; z3 = own.w; z4 = a;
        } break;
        case 1: {
            float a = __shfl_down_sync(FULL, own.x, 1);      // z[4l+3]
            float b = __shfl_down_sync(FULL, own.y, 1);      // z[4l+4]
            if (lane == 31) { a = __ldg(zrow + 127); b = __ldg(zrow + 128); }
            zm1 = own.x; z0 = own.y; z1 = own.z; z2 = own.w; z3 = a; z4 = b;
        } break;
        case 2: {
            float a = __shfl_down_sync(FULL, own.x, 1);      // z[4l+2]
            float b = __shfl_down_sync(FULL, own.y, 1);      // z[4l+3]
            float c = __shfl_down_sync(FULL, own.z, 1);      // z[4l+4]
            if (lane == 31) { a = __ldg(zrow + 126); b = __ldg(zrow + 127);
                              c = __ldg(zrow + 128); }
            zm1 = own.y; z0 = own.z; z1 = own.w; z2 = a; z3 = b; z4 = c;
        } break;
        default: {
            float a = __shfl_down_sync(FULL, own.x, 1);      // z[4l+1]
            float b = __shfl_down_sync(FULL, own.y, 1);      // z[4l+2]
            float c = __shfl_down_sync(FULL, own.z, 1);      // z[4l+3]
            float d = __shfl_down_sync(FULL, own.w, 1);      // z[4l+4]
            if (lane == 31) { a = __ldg(zrow + 125); b = __ldg(zrow + 126);
                              c = __ldg(zrow + 127); d = __ldg(zrow + 128); }
            zm1 = own.z; z0 = own.w; z1 = a; z2 = b; z3 = c; z4 = d;
        } break;
    }

    // ---- lane-local w prefixes ----
    const float pre1 = w4.x;
    const float pre2 = pre1 + w4.y;
    const float pre3 = pre2 + w4.z;
    const float wc   = pre3 + w4.w;

    // ---- warp inclusive scan of lane totals ----
    float wInc = wc;
#pragma unroll
    for (int o = 1; o < 32; o <<= 1) {
        float t = __shfl_up_sync(FULL, wInc, o);
        if (lane >= o) wInc += t;
    }
    const float Wex = wInc - wc;
    const float T   = __shfl_sync(FULL, wInc, 31);

    // ---- gaps + prefix products ----
    const float g0 = z1 - zm1;
    const float g1 = z2 - z0;
    const float g2 = z3 - z1;
    const float g3 = z4 - z2;

    const float P0 = Wex;
    const float P1 = Wex + pre1;
    const float P2 = Wex + pre2;
    const float P3 = Wex + pre3;

    const float t0 = g0 * P0;
    const float t1 = g1 * P1;
    const float t2 = g2 * P2;
    const float t3 = g3 * P3;

    const float A = (t0 + t1) + (t2 + t3);

    float C;
    C =      (w4.x * w4.x) * (z1 - z0);
    C = fmaf((w4.y * w4.y), (z2 - z1), C);
    C = fmaf((w4.z * w4.z), (z3 - z2), C);
    C = fmaf((w4.w * w4.w), (z4 - z3), C);
    C *= (1.0f / 3.0f);
    C = fmaf(-t0, P0, C);
    C = fmaf(-t1, P1, C);
    C = fmaf(-t2, P2, C);
    C = fmaf(-t3, P3, C);

    // T known to all lanes -> combine BEFORE a single butterfly
    float partial = fmaf(T, A, C);
#pragma unroll
    for (int o = 16; o > 0; o >>= 1)
        partial += __shfl_xor_sync(FULL, partial, o);

    if (lane == 0)
        out[row] = partial * inv;
}

extern "C" void kernel_launch(void* const* d_in, const int* in_sizes, int n_in,
                              void* d_out, int out_size)
{
    const float* w  = (const float*)d_in[0];   // (R, 128, 1)
    const float* z  = (const float*)d_in[1];   // (R, 129)
    const float* nr = (const float*)d_in[2];   // (R, 1)
    const float* fr = (const float*)d_in[3];   // (R, 1)
    float* out = (float*)d_out;                // (R, 1)

    const int R = in_sizes[0] / 128;
    const int threads = 256;                   // 8 warps = 8 rows per block
    const int rowsPerBlock = threads / 32;
    if (R % rowsPerBlock == 0) {
        // exact cover: no per-warp bounds guard
        distortion_loss_kernel<false><<<R / rowsPerBlock, threads>>>(w, z, nr, fr, out, R);
    } else {
        distortion_loss_kernel<true><<<(R + rowsPerBlock - 1) / rowsPerBlock, threads>>>(w, z, nr, fr, out, R);
    }
}

// round 14
// speedup vs baseline: 1.1354x; 1.1354x over previous
#include <cuda_runtime.h>
#include <cuda_bf16.h>
#include <cstdint>

// DistortionLoss, O(N) per row, telescoped + T-deferred:
//   loss = inv * [ T*sum_e g_e*P_e - sum_e g_e*P_e^2 + (1/3)*sum w_i^2*dz_i ]
//   g_e = z_{e+1}-z_{e-1}, P_e = exclusive w prefix, T = total w,
//   inv = 1/(far-near). The e=0 term has P_0 = 0, so lane 0's zm1 is a
//   don't-care (any in-bounds value).
//
// Converged configuration (14 rounds of measurement):
//  - O(N^2) pairwise sum reduced to O(N) via sorted-midpoint prefix identity,
//    then telescoped so near/far and all per-element normalization vanish.
//  - z loaded as ONE aligned LDG.128 per lane from the 16B-floor base
//    (row*129 - s, s = row&3): minimal L1tex wavefronts (~11/warp) — the
//    only reproducible ncu win of the series (L1% 21 -> 14).
//  - minimal warp-uniform shfl recovery (avg 2.75 shfls vs 5).
//  - single irreducible warp scan (Wex); T pre-combined before one
//    5-step butterfly.
//  - MUFU.RCP hoisted to overlap the shfl chains.
//  - 256-thread blocks, grid 1024: source of the two best ncu samples.
// Kernel is at its launch-ramp + DRAM-latency floor (~5.6-6.3 us ncu).

#define FULL 0xffffffffu

__global__ __launch_bounds__(256)
void distortion_loss_kernel(const float* __restrict__ w,
                            const float* __restrict__ z,
                            const float* __restrict__ nearv,
                            const float* __restrict__ farv,
                            float* __restrict__ out,
                            int R)
{
    const int row  = (blockIdx.x * blockDim.x + threadIdx.x) >> 5;
    const int lane = threadIdx.x & 31;
    if (row >= R) return;

    const int s = row & 3;                                   // warp-uniform
    const float* zrow = z + (size_t)row * 129;
    const float4* zc  = reinterpret_cast<const float4*>(zrow - s);  // aligned

    // ---- front-batched loads ----
    const float4 own = __ldg(zc + lane);                     // z[4l-s .. 4l-s+3]
    const float4 w4  = __ldg(reinterpret_cast<const float4*>(w + (size_t)row * 128) + lane);
    const float nr = __ldg(&nearv[row]);
    const float fr = __ldg(&farv[row]);

    // reciprocal issued early: MUFU latency overlaps the shfl chains below
    const float inv = __fdividef(1.0f, fr - nr);

    // ---- recover z[4l-1 .. 4l+4] with minimal shfls (warp-uniform switch) ----
    float zm1, z0, z1, z2, z3, z4;
    switch (s) {
        case 0: {
            float a = __shfl_down_sync(FULL, own.x, 1);      // z[4l+4]
            float b = __shfl_up_sync(FULL, own.w, 1);        // z[4l-1] (lane0 dc)
            if (lane == 31) a = __ldg(zrow + 128);
            zm1 = b; z0 = own.x; z1 = own.y; z2 = own.z; z3 = own.w; z4 = a;
        } break;
        case 1: {
            float a = __shfl_down_sync(FULL, own.x, 1);      // z[4l+3]
            float b = __shfl_down_sync(FULL, own.y, 1);      // z[4l+4]
            if (lane == 31) { a = __ldg(zrow + 127); b = __ldg(zrow + 128); }
            zm1 = own.x; z0 = own.y; z1 = own.z; z2 = own.w; z3 = a; z4 = b;
        } break;
        case 2: {
            float a = __shfl_down_sync(FULL, own.x, 1);      // z[4l+2]
            float b = __shfl_down_sync(FULL, own.y, 1);      // z[4l+3]
            float c = __shfl_down_sync(FULL, own.z, 1);      // z[4l+4]
            if (lane == 31) { a = __ldg(zrow + 126); b = __ldg(zrow + 127);
                              c = __ldg(zrow + 128); }
            zm1 = own.y; z0 = own.z; z1 = own.w; z2 = a; z3 = b; z4 = c;
        } break;
        default: {
            float a = __shfl_down_sync(FULL, own.x, 1);      // z[4l+1]
            float b = __shfl_down_sync(FULL, own.y, 1);      // z[4l+2]
            float c = __shfl_down_sync(FULL, own.z, 1);      // z[4l+3]
            float d = __shfl_down_sync(FULL, own.w, 1);      // z[4l+4]
            if (lane == 31) { a = __ldg(zrow + 125); b = __ldg(zrow + 126);
                              c = __ldg(zrow + 127); d = __ldg(zrow + 128); }
            zm1 = own.z; z0 = own.w; z1 = a; z2 = b; z3 = c; z4 = d;
        } break;
    }

    // ---- lane-local w prefixes ----
    const float pre1 = w4.x;
    const float pre2 = pre1 + w4.y;
    const float pre3 = pre2 + w4.z;
    const float wc   = pre3 + w4.w;

    // ---- warp inclusive scan of lane totals (irreducible) ----
    float wInc = wc;
#pragma unroll
    for (int o = 1; o < 32; o <<= 1) {
        float t = __shfl_up_sync(FULL, wInc, o);
        if (lane >= o) wInc += t;
    }
    const float Wex = wInc - wc;
    const float T   = __shfl_sync(FULL, wInc, 31);

    // ---- gaps + prefix products ----
    const float g0 = z1 - zm1;
    const float g1 = z2 - z0;
    const float g2 = z3 - z1;
    const float g3 = z4 - z2;

    const float P0 = Wex;
    const float P1 = Wex + pre1;
    const float P2 = Wex + pre2;
    const float P3 = Wex + pre3;

    const float t0 = g0 * P0;
    const float t1 = g1 * P1;
    const float t2 = g2 * P2;
    const float t3 = g3 * P3;

    const float A = (t0 + t1) + (t2 + t3);

    float C;
    C =      (w4.x * w4.x) * (z1 - z0);
    C = fmaf((w4.y * w4.y), (z2 - z1), C);
    C = fmaf((w4.z * w4.z), (z3 - z2), C);
    C = fmaf((w4.w * w4.w), (z4 - z3), C);
    C *= (1.0f / 3.0f);
    C = fmaf(-t0, P0, C);
    C = fmaf(-t1, P1, C);
    C = fmaf(-t2, P2, C);
    C = fmaf(-t3, P3, C);

    // T known to all lanes -> combine BEFORE a single butterfly
    float partial = fmaf(T, A, C);
#pragma unroll
    for (int o = 16; o > 0; o >>= 1)
        partial += __shfl_xor_sync(FULL, partial, o);

    if (lane == 0)
        out[row] = partial * inv;
}

extern "C" void kernel_launch(void* const* d_in, const int* in_sizes, int n_in,
                              void* d_out, int out_size)
{
    const float* w  = (const float*)d_in[0];   // (R, 128, 1)
    const float* z  = (const float*)d_in[1];   // (R, 129)
    const float* nr = (const float*)d_in[2];   // (R, 1)
    const float* fr = (const float*)d_in[3];   // (R, 1)
    float* out = (float*)d_out;                // (R, 1)

    const int R = in_sizes[0] / 128;
    const int threads = 256;                   // 8 warps = 8 rows per block
    const int blocks  = (R * 32 + threads - 1) / threads;   // 1024 for R=8192
    distortion_loss_kernel<<<blocks, threads>>>(w, z, nr, fr, out, R);
}